// round 11
// baseline (speedup 1.0000x reference)
#include <cuda_runtime.h>
#include <cuda_fp16.h>
#include <cstdint>
#include <cstddef>

#define T_   512
#define B_   128
#define H_   512
#define G4   2048
#define CLU  16      // CTAs per cluster/group

// ---------------- scratch (device globals; no allocation) ----------------
__device__ __half        g_Xg[(size_t)T_ * B_ * G4];     // 256 MB fp16 Xg
__device__ __half        g_lat16[(size_t)T_ * B_ * 512]; // 64 MB tiled latent
__device__ uint32_t      g_w16p[16 * 16 * 2 * 128 * 8];  // 2 MB W_ih smem-ready
__device__ unsigned char g_slc[2][8][CLU][1024];         // h slices, fragment order

// ---------------- helpers ----------------
__device__ __forceinline__ void mma_f16(float c[4], const uint32_t a[4],
                                        uint32_t b0, uint32_t b1) {
    asm volatile(
        "mma.sync.aligned.m16n8k16.row.col.f32.f16.f16.f32 "
        "{%0,%1,%2,%3},{%4,%5,%6,%7},{%8,%9},{%0,%1,%2,%3};"
        : "+f"(c[0]), "+f"(c[1]), "+f"(c[2]), "+f"(c[3])
        : "r"(a[0]), "r"(a[1]), "r"(a[2]), "r"(a[3]), "r"(b0), "r"(b1));
}
__device__ __forceinline__ void ldsm4(uint32_t r[4], uint32_t saddr) {
    asm volatile("ldmatrix.sync.aligned.m8n8.x4.shared.b16 {%0,%1,%2,%3},[%4];"
        : "=r"(r[0]), "=r"(r[1]), "=r"(r[2]), "=r"(r[3]) : "r"(saddr));
}
__device__ __forceinline__ void cp16(uint32_t sdst, const void* gsrc) {
    asm volatile("cp.async.ca.shared.global [%0],[%1],16;" :: "r"(sdst), "l"(gsrc));
}
__device__ __forceinline__ uint32_t h2u(float x, float y) {
    __half2 h = __floats2half2_rn(x, y);
    return *reinterpret_cast<uint32_t*>(&h);
}
__device__ __forceinline__ float sigf(float x) {
    return __fdividef(1.0f, 1.0f + __expf(-x));
}
__device__ __forceinline__ float tanhfast(float x) {
    return 1.0f - 2.0f * __fdividef(1.0f, __expf(2.0f * x) + 1.0f);
}
__device__ __forceinline__ uint32_t ctarank() {
    uint32_t r; asm("mov.u32 %0, %%cluster_ctarank;" : "=r"(r)); return r;
}
// global -> all cluster CTAs' smem (same offset), complete_tx on each CTA's mbar
__device__ __forceinline__ void bulk_mc(uint32_t sdst, const void* gsrc,
                                        uint32_t bytes, uint32_t mbar, uint16_t mask) {
    asm volatile(
        "cp.async.bulk.shared::cluster.global.mbarrier::complete_tx::bytes"
        ".multicast::cluster [%0], [%1], %2, [%3], %4;"
        :: "r"(sdst), "l"(gsrc), "r"(bytes), "r"(mbar), "h"(mask) : "memory");
}

// ==========================================================================
// Convert latent -> fp16, tiled layout [(tt*16+kt)*128 + r][32]   (R10)
// ==========================================================================
__global__ void __launch_bounds__(256) conv_lat(const float* __restrict__ latent) {
    const size_t n = (size_t)T_ * B_ * 512 / 2;
    uint32_t* dst = reinterpret_cast<uint32_t*>(g_lat16);
    for (size_t i = (size_t)blockIdx.x * 256 + threadIdx.x; i < n;
         i += (size_t)gridDim.x * 256) {
        size_t hidx = i * 2;
        int    k    = (int)(hidx & 31);
        size_t rest = hidx >> 5;
        int    r    = (int)(rest & 127);
        size_t r2   = rest >> 7;
        int    kt   = (int)(r2 & 15);
        size_t tt   = r2 >> 4;
        size_t src  = (tt * 128 + r) * 512 + kt * 32 + k;
        float2 v = *reinterpret_cast<const float2*>(&latent[src]);
        dst[i] = h2u(v.x, v.y);
    }
}

// ==========================================================================
// Convert w_ih -> fp16 permuted smem layout (R10)
// ==========================================================================
__global__ void __launch_bounds__(256) conv_w(const float* __restrict__ w_ih) {
    const int total = 16 * 16 * 2 * 128 * 8;
    for (int d = blockIdx.x * 256 + threadIdx.x; d < total; d += gridDim.x * 256) {
        int q  = d & 7, r = (d >> 3) & 127, ks = (d >> 10) & 1;
        int kt = (d >> 11) & 15, nt = d >> 15;
        int p  = (q & 1) ? (4 + (q >> 1)) : (q >> 1);
        int k  = kt * 32 + ks * 16 + p * 2;
        int n  = nt * 128 + r;
        float2 v = *reinterpret_cast<const float2*>(&w_ih[(size_t)n * 512 + k]);
        g_w16p[d] = h2u(v.x, v.y);
    }
}

// ==========================================================================
// Phase 1: Xg = latent @ W_ih^T + bias -> fp16. 4-stage cp.async ring (R10).
// ==========================================================================
__global__ void __launch_bounds__(256, 2) xgemm_fp16(
    const float* __restrict__ b_ih, const float* __restrict__ b_hh)
{
    extern __shared__ __align__(16) unsigned char sm[];
    float* bias_s = (float*)sm;

    const int tid  = threadIdx.x;
    const int nt   = blockIdx.x & 15;
    const int tt   = blockIdx.x >> 4;
    const int n0   = nt * 128;
    const int lane = tid & 31, w = tid >> 5;
    const int mb   = (w & 3) * 32;
    const int nb2  = (w >> 2) * 64;

    if (tid < 128) bias_s[tid] = b_ih[n0 + tid] + b_hh[n0 + tid];

    const uint32_t smBase = (uint32_t)__cvta_generic_to_shared(sm);

    float c[2][8][4];
    #pragma unroll
    for (int i = 0; i < 2; i++)
        #pragma unroll
        for (int jx = 0; jx < 8; jx++)
            #pragma unroll
            for (int k = 0; k < 4; k++) c[i][jx][k] = 0.f;

    auto ISSUE = [&](int kt, int s) {
        uint32_t Aa = smBase + 512 + s * 18432;
        uint32_t Ba = Aa + 10240;
        const __half* asrc = g_lat16 + ((size_t)(tt * 16 + kt) << 12);
        #pragma unroll
        for (int i = 0; i < 2; i++) {
            int cch = tid + i * 256;
            int r = cch >> 2, c4 = cch & 3;
            cp16(Aa + r * 80 + c4 * 16, asrc + r * 32 + c4 * 8);
        }
        const uint32_t* wsrc = g_w16p + (size_t)(nt * 16 + kt) * 2048;
        #pragma unroll
        for (int i = 0; i < 2; i++) {
            int cch = tid + i * 256;
            cp16(Ba + cch * 16, wsrc + cch * 4);
        }
        asm volatile("cp.async.commit_group;");
    };

    auto COMPUTE = [&](int s) {
        const uint32_t* Au = (const uint32_t*)(sm + 512 + s * 18432);
        const uint32_t* Bs = (const uint32_t*)(sm + 512 + s * 18432 + 10240);
        #pragma unroll
        for (int ks = 0; ks < 2; ++ks) {
            uint32_t a[2][4];
            #pragma unroll
            for (int mi = 0; mi < 2; mi++) {
                int base = (mb + mi * 16 + (lane >> 2)) * 20 + ks * 8 + (lane & 3);
                a[mi][0] = Au[base];       a[mi][1] = Au[base + 160];
                a[mi][2] = Au[base + 4];   a[mi][3] = Au[base + 164];
            }
            #pragma unroll
            for (int ni = 0; ni < 8; ++ni) {
                int n = nb2 + ni * 8 + (lane >> 2);
                uint2 bv = *reinterpret_cast<const uint2*>(&Bs[(ks * 128 + n) * 8 + (lane & 3) * 2]);
                mma_f16(c[0][ni], a[0], bv.x, bv.y);
                mma_f16(c[1][ni], a[1], bv.x, bv.y);
            }
        }
    };

    ISSUE(0, 0); ISSUE(1, 1); ISSUE(2, 2);
    #pragma unroll 1
    for (int kt = 0; kt < 16; ++kt) {
        if (kt <= 13)      asm volatile("cp.async.wait_group 2;");
        else if (kt == 14) asm volatile("cp.async.wait_group 1;");
        else               asm volatile("cp.async.wait_group 0;");
        __syncthreads();
        COMPUTE(kt & 3);
        if (kt + 3 < 16) ISSUE(kt + 3, (kt + 3) & 3);
    }

    #pragma unroll
    for (int mi = 0; mi < 2; mi++) {
        #pragma unroll
        for (int ni = 0; ni < 8; ni++) {
            int r    = mb + mi * 16 + (lane >> 2);
            int colL = nb2 + ni * 8 + (lane & 3) * 2;
            float bv0 = bias_s[colL], bv1 = bias_s[colL + 1];
            size_t base = ((size_t)(tt * 128 + r)) * G4 + n0 + colL;
            *reinterpret_cast<uint32_t*>(&g_Xg[base]) =
                h2u(c[mi][ni][0] + bv0, c[mi][ni][1] + bv1);
            *reinterpret_cast<uint32_t*>(&g_Xg[base + (size_t)8 * G4]) =
                h2u(c[mi][ni][2] + bv0, c[mi][ni][3] + bv1);
        }
    }
}

// ==========================================================================
// Phase 2: persistent recurrence, 8 clusters x 16 CTAs.
// h handoff: producer STGs its 1KB slice (pre-formatted in mma A-fragment
// order) to global, then one multicast bulk load delivers it into all 16
// peers' smem A buffer with mbarrier complete_tx. No flags, no polls,
// no restaging; GEMM reads A via conflict-free LDS.128.
// smem: A0 @0 (16384) | A1 @16384 | mbar @33024 (2 x u64); W init region
// [0,196608) aliases (used only before the loop). W_hh frags in registers.
// ==========================================================================
__global__ void __launch_bounds__(256, 1) lstm_rec_mc(
    const float*    __restrict__ h0,
    const float*    __restrict__ c0,
    const uint32_t* __restrict__ reset,    // [B,T]
    const uint32_t* __restrict__ clearm,   // [B,T]
    const float*    __restrict__ nstd,     // [B,T]
    const float*    __restrict__ noise,    // [T,B,H]
    const float*    __restrict__ w_hh,     // [2048,512]
    float*          __restrict__ out)
{
    extern __shared__ __align__(16) unsigned char sm[];

    const int tid  = threadIdx.x;
    const int lane = tid & 31, w = tid >> 5;
    const int cg   = (int)ctarank();
    const int mg   = blockIdx.x >> 4;
    const int b0   = mg * 16, j0 = cg * 32;
    const unsigned FM = 0xFFFFFFFFu;

    const uint32_t smBase = (uint32_t)__cvta_generic_to_shared(sm);
    const uint32_t mb0    = smBase + 33024;

    // ---- W region fill (once), permuted col order (warp w: {i,f|g,o} of its 4 cols)
    for (int e = tid; e < 4096; e += 256) {
        int ks = e >> 7, c = e & 127;
        int wp = c >> 4, idx = c & 15;
        int ti = idx >> 3, p = idx & 7;
        int n  = (ti * 2 + (p >> 2)) * 512 + j0 + wp * 4 + (p & 3);
        const float4* wpn = reinterpret_cast<const float4*>(&w_hh[(size_t)n * 512 + ks * 16]);
        float4 w0 = wpn[0], w1 = wpn[1], w2 = wpn[2], w3 = wpn[3];
        uint4 lo, hi;
        lo.x = h2u(w0.x, w0.y); lo.y = h2u(w0.z, w0.w);
        lo.z = h2u(w1.x, w1.y); lo.w = h2u(w1.z, w1.w);
        hi.x = h2u(w2.x, w2.y); hi.y = h2u(w2.z, w2.w);
        hi.z = h2u(w3.x, w3.y); hi.w = h2u(w3.z, w3.w);
        char* base = (char*)sm + (size_t)(ks * 128 + c) * 48;
        *reinterpret_cast<uint4*>(base)      = lo;
        *reinterpret_cast<uint4*>(base + 16) = hi;
    }
    __syncthreads();

    // ---- load all W_hh fragments into registers
    const int mq = lane >> 3, rl = lane & 7;
    const int rowL = (mq & 1) * 8 + rl;
    const int koff = (mq >> 1) * 8;
    const uint32_t bAddr0 = smBase + (w * 16 + rowL) * 48 + koff * 2;
    uint32_t bb[32][4];
    #pragma unroll
    for (int ks = 0; ks < 32; ++ks)
        ldsm4(bb[ks], bAddr0 + ks * 6144);
    __syncthreads();   // W region now free; A buffers alias it

    // ---- mbar init + arm expect(0), expect(1); then cluster sync
    if (tid == 0) {
        asm volatile("mbarrier.init.shared.b64 [%0], 1;" :: "r"(mb0) : "memory");
        asm volatile("mbarrier.init.shared.b64 [%0], 1;" :: "r"(mb0 + 8) : "memory");
        asm volatile("mbarrier.arrive.expect_tx.shared.b64 _, [%0], %1;"
                     :: "r"(mb0), "r"(16384u) : "memory");
        asm volatile("mbarrier.arrive.expect_tx.shared.b64 _, [%0], %1;"
                     :: "r"(mb0 + 8), "r"(16384u) : "memory");
    }
    __syncthreads();
    asm volatile("barrier.cluster.arrive.aligned;" ::: "memory");
    asm volatile("barrier.cluster.wait.aligned;" ::: "memory");

    // ---- epilogue / slice-scatter lane mapping
    const int rE = lane >> 2, jE = lane & 3;
    const int bA = b0 + rE, bB = bA + 8;
    const int jl = w * 4 + jE;            // local col 0..31
    const int j  = j0 + jl;
    const int sA = (lane & 28) | (jE >> 1);
    const int sB = sA | 2;
    const int kk  = jl & 15;
    const int slcOff = (jl >> 4) * 512 + (rE * 4 + ((kk & 7) >> 1)) * 16
                     + ((kk >= 8) ? 8 : 0) + (kk & 1) * 2;   // row rE; rE+8 at +4

    // ---- init h/c with step-0 preprocessing; publish slice 0
    float cst0, cst1;
    {
        float hA = h0[bA * H_ + j], cA = c0[bA * H_ + j];
        float hB = h0[bB * H_ + j], cB = c0[bB * H_ + j];
        bool mA = ((reset[bA * T_] | clearm[bA * T_]) != 0u);
        bool mB = ((reset[bB * T_] | clearm[bB * T_]) != 0u);
        if (mA) { hA = cA = 0.f; }
        if (mB) { hB = cB = 0.f; }
        float nzA = noise[(size_t)bA * H_ + j] * nstd[bA * T_];
        float nzB = noise[(size_t)bB * H_ + j] * nstd[bB * T_];
        hA += nzA; cA += nzA;
        hB += nzB; cB += nzB;
        unsigned char* sp = &g_slc[0][mg][cg][0];
        *(__half*)(sp + slcOff)     = __float2half_rn(hA);
        *(__half*)(sp + slcOff + 4) = __float2half_rn(hB);
        cst0 = cA; cst1 = cB;
    }
    __syncthreads();
    if (tid == 0) {
        asm volatile("membar.gl;" ::: "memory");
        asm volatile("fence.proxy.async;" ::: "memory");
        bulk_mc(smBase + cg * 1024, &g_slc[0][mg][cg][0], 1024u, mb0, (uint16_t)0xFFFF);
    }

    for (int t = 0; t < T_; ++t) {
        // ---- prefetch (independent of h[t]) ----
        size_t xbA = ((size_t)t * B_ + bA) * G4 + j;
        size_t xbB = ((size_t)t * B_ + bB) * G4 + j;
        float xI0 = __half2float(g_Xg[xbA]),        xI1 = __half2float(g_Xg[xbB]);
        float xF0 = __half2float(g_Xg[xbA + 512]),  xF1 = __half2float(g_Xg[xbB + 512]);
        float xG0 = __half2float(g_Xg[xbA + 1024]), xG1 = __half2float(g_Xg[xbB + 1024]);
        float xO0 = __half2float(g_Xg[xbA + 1536]), xO1 = __half2float(g_Xg[xbB + 1536]);
        unsigned mN0 = 0, mN1 = 0;
        float sN0 = 0.f, sN1 = 0.f, nz0 = 0.f, nz1 = 0.f;
        if (t + 1 < T_) {
            mN0 = reset[bA * T_ + t + 1] | clearm[bA * T_ + t + 1];
            mN1 = reset[bB * T_ + t + 1] | clearm[bB * T_ + t + 1];
            sN0 = nstd[bA * T_ + t + 1];
            sN1 = nstd[bB * T_ + t + 1];
            nz0 = noise[((size_t)(t + 1) * B_ + bA) * H_ + j];
            nz1 = noise[((size_t)(t + 1) * B_ + bB) * H_ + j];
        }

        // ---- wait for all 16 slices of step t (mbarrier, HW sleep) ----
        {
            uint32_t mb = mb0 + (t & 1) * 8;
            uint32_t ph = (t >> 1) & 1;
            asm volatile(
                "{\n\t.reg .pred P;\n"
                "WAITL_%=:\n\t"
                "mbarrier.try_wait.parity.acquire.cta.shared::cta.b64 P, [%0], %1, 0x989680;\n\t"
                "@!P bra WAITL_%=;\n\t}"
                :: "r"(mb), "r"(ph) : "memory");
        }
        // arm expect(t+2) — after wait(t), before our copy(t+1) (race-free chain)
        if (tid == 0 && t + 2 < T_)
            asm volatile("mbarrier.arrive.expect_tx.shared.b64 _, [%0], %1;"
                         :: "r"(mb0 + (t & 1) * 8), "r"(16384u) : "memory");

        // ---- GEMM: 32 ksteps, A via conflict-free LDS.128 (fragment order) ----
        const unsigned char* Ab = sm + (t & 1) * 16384;
        float a0A[4] = {0.f, 0.f, 0.f, 0.f}, a1A[4] = {0.f, 0.f, 0.f, 0.f};
        float a0B[4] = {0.f, 0.f, 0.f, 0.f}, a1B[4] = {0.f, 0.f, 0.f, 0.f};
        #pragma unroll
        for (int ks = 0; ks < 32; ks += 2) {
            uint4 v1 = *reinterpret_cast<const uint4*>(
                Ab + (ks >> 1) * 1024 + lane * 16);
            uint4 v2 = *reinterpret_cast<const uint4*>(
                Ab + (ks >> 1) * 1024 + 512 + lane * 16);
            uint32_t a[4]  = {v1.x, v1.y, v1.z, v1.w};
            uint32_t a2[4] = {v2.x, v2.y, v2.z, v2.w};
            mma_f16(a0A, a,  bb[ks][0],     bb[ks][2]);
            mma_f16(a1A, a,  bb[ks][1],     bb[ks][3]);
            mma_f16(a0B, a2, bb[ks + 1][0], bb[ks + 1][2]);
            mma_f16(a1B, a2, bb[ks + 1][1], bb[ks + 1][3]);
        }
        float acc0[4], acc1[4];
        #pragma unroll
        for (int i = 0; i < 4; i++) {
            acc0[i] = a0A[i] + a0B[i];
            acc1[i] = a1A[i] + a1B[i];
        }

        // ---- in-warp gate exchange (shfl only) ----
        float u0, u1;
        u0 = __shfl_sync(FM, acc0[0], sA); u1 = __shfl_sync(FM, acc0[1], sA);
        float gi0 = (jE & 1) ? u1 : u0;
        u0 = __shfl_sync(FM, acc0[2], sA); u1 = __shfl_sync(FM, acc0[3], sA);
        float gi1 = (jE & 1) ? u1 : u0;
        u0 = __shfl_sync(FM, acc0[0], sB); u1 = __shfl_sync(FM, acc0[1], sB);
        float gf0 = (jE & 1) ? u1 : u0;
        u0 = __shfl_sync(FM, acc0[2], sB); u1 = __shfl_sync(FM, acc0[3], sB);
        float gf1 = (jE & 1) ? u1 : u0;
        u0 = __shfl_sync(FM, acc1[0], sA); u1 = __shfl_sync(FM, acc1[1], sA);
        float gg0 = (jE & 1) ? u1 : u0;
        u0 = __shfl_sync(FM, acc1[2], sA); u1 = __shfl_sync(FM, acc1[3], sA);
        float gg1 = (jE & 1) ? u1 : u0;
        u0 = __shfl_sync(FM, acc1[0], sB); u1 = __shfl_sync(FM, acc1[1], sB);
        float go0 = (jE & 1) ? u1 : u0;
        u0 = __shfl_sync(FM, acc1[2], sB); u1 = __shfl_sync(FM, acc1[3], sB);
        float go1 = (jE & 1) ? u1 : u0;

        // ---- gates + state update ----
        float iA = sigf(gi0 + xI0),     iB = sigf(gi1 + xI1);
        float fA = sigf(gf0 + xF0),     fB = sigf(gf1 + xF1);
        float gA = tanhfast(gg0 + xG0), gB = tanhfast(gg1 + xG1);
        float oA = sigf(go0 + xO0),     oB = sigf(go1 + xO1);

        float cnA = fA * cst0 + iA * gA;
        float cnB = fB * cst1 + iB * gB;
        float hnA = oA * tanhfast(cnA);
        float hnB = oB * tanhfast(cnB);

        // ---- publish h[t+1] slice via multicast ----
        if (t + 1 < T_) {
            float hwA = mN0 ? 0.f : hnA, cwA = mN0 ? 0.f : cnA;
            float hwB = mN1 ? 0.f : hnB, cwB = mN1 ? 0.f : cnB;
            hwA += nz0 * sN0; cwA += nz0 * sN0;
            hwB += nz1 * sN1; cwB += nz1 * sN1;
            cst0 = cwA; cst1 = cwB;

            unsigned char* sp = &g_slc[(t + 1) & 1][mg][cg][0];
            *(__half*)(sp + slcOff)     = __float2half_rn(hwA);
            *(__half*)(sp + slcOff + 4) = __float2half_rn(hwB);
            __syncthreads();
            if (tid == 0) {
                asm volatile("membar.gl;" ::: "memory");
                asm volatile("fence.proxy.async;" ::: "memory");
                bulk_mc(smBase + (uint32_t)(((t + 1) & 1) * 16384) + cg * 1024,
                        sp, 1024u, mb0 + ((t + 1) & 1) * 8, (uint16_t)0xFFFF);
            }
        } else {
            out[(size_t)T_ * (B_ * H_)           + bA * H_ + j] = hnA;
            out[(size_t)T_ * (B_ * H_)           + bB * H_ + j] = hnB;
            out[(size_t)T_ * (B_ * H_) + B_ * H_ + bA * H_ + j] = cnA;
            out[(size_t)T_ * (B_ * H_) + B_ * H_ + bB * H_ + j] = cnB;
        }

        // ---- off-critical-path output stores ----
        out[((size_t)t * B_ + bA) * H_ + j] = hnA;
        out[((size_t)t * B_ + bB) * H_ + j] = hnB;
    }

    asm volatile("barrier.cluster.arrive.aligned;" ::: "memory");
    asm volatile("barrier.cluster.wait.aligned;" ::: "memory");
}

// ==========================================================================
extern "C" void kernel_launch(void* const* d_in, const int* in_sizes, int n_in,
                              void* d_out, int out_size) {
    (void)in_sizes; (void)n_in; (void)out_size;
    const float*    latent = (const float*)d_in[0];
    const float*    h0     = (const float*)d_in[1];
    const float*    c0     = (const float*)d_in[2];
    const uint32_t* reset  = (const uint32_t*)d_in[3];
    const uint32_t* clearm = (const uint32_t*)d_in[4];
    const float*    nstd   = (const float*)d_in[5];
    const float*    noise  = (const float*)d_in[6];
    const float*    w_ih   = (const float*)d_in[7];
    const float*    w_hh   = (const float*)d_in[8];
    const float*    b_ih   = (const float*)d_in[9];
    const float*    b_hh   = (const float*)d_in[10];
    float* out = (float*)d_out;

    const int smem1 = 512 + 4 * 18432;                 // 74240 B
    const int smem2 = 196608;                          // A bufs + mbar alias inside
    cudaFuncSetAttribute(xgemm_fp16, cudaFuncAttributeMaxDynamicSharedMemorySize, smem1);
    cudaFuncSetAttribute(lstm_rec_mc, cudaFuncAttributeMaxDynamicSharedMemorySize, smem2);
    cudaFuncSetAttribute(lstm_rec_mc, cudaFuncAttributeNonPortableClusterSizeAllowed, 1);

    conv_lat<<<4096, 256>>>(latent);
    conv_w<<<512, 256>>>(w_ih);
    xgemm_fp16<<<512 * 16, 256, smem1>>>(b_ih, b_hh);

    cudaLaunchConfig_t cfg = {};
    cfg.gridDim  = dim3(128, 1, 1);
    cfg.blockDim = dim3(256, 1, 1);
    cfg.dynamicSmemBytes = smem2;
    cudaLaunchAttribute attrs[1];
    attrs[0].id = cudaLaunchAttributeClusterDimension;
    attrs[0].val.clusterDim.x = CLU;
    attrs[0].val.clusterDim.y = 1;
    attrs[0].val.clusterDim.z = 1;
    cfg.attrs = attrs;
    cfg.numAttrs = 1;
    cudaLaunchKernelEx(&cfg, lstm_rec_mc,
                       h0, c0, reset, clearm, nstd, noise, w_hh, out);
}

// round 12
// speedup vs baseline: 1.5086x; 1.5086x over previous
#include <cuda_runtime.h>
#include <cuda_fp16.h>
#include <cstdint>
#include <cstddef>

#define T_   512
#define B_   128
#define H_   512
#define G4   2048
#define NG   16      // CTAs per row-group (phase 2)

// ---------------- scratch (device globals; no allocation) ----------------
__device__ __half   g_Xg[(size_t)T_ * B_ * G4];     // 256 MB fp16: x@W_ih^T + bias
__device__ __half   g_lat16[(size_t)T_ * B_ * 512]; // 64 MB, tiled [tt][kt][r][32]
__device__ uint32_t g_w16p[16 * 16 * 2 * 128 * 8];  // 2 MB, smem-layout-ready
__device__ __half   g_h2[2][B_ * H_];               // double-buffered fp16 h
__device__ unsigned g_flag[8][T_ + 1][NG];          // per-group per-step flags

// ---------------- helpers ----------------
__device__ __forceinline__ void mma_f16(float c[4], const uint32_t a[4],
                                        uint32_t b0, uint32_t b1) {
    asm volatile(
        "mma.sync.aligned.m16n8k16.row.col.f32.f16.f16.f32 "
        "{%0,%1,%2,%3},{%4,%5,%6,%7},{%8,%9},{%0,%1,%2,%3};"
        : "+f"(c[0]), "+f"(c[1]), "+f"(c[2]), "+f"(c[3])
        : "r"(a[0]), "r"(a[1]), "r"(a[2]), "r"(a[3]), "r"(b0), "r"(b1));
}
__device__ __forceinline__ void ldsm4(uint32_t r[4], uint32_t saddr) {
    asm volatile("ldmatrix.sync.aligned.m8n8.x4.shared.b16 {%0,%1,%2,%3},[%4];"
        : "=r"(r[0]), "=r"(r[1]), "=r"(r[2]), "=r"(r[3]) : "r"(saddr));
}
__device__ __forceinline__ void cp16(uint32_t sdst, const void* gsrc) {
    asm volatile("cp.async.ca.shared.global [%0],[%1],16;" :: "r"(sdst), "l"(gsrc));
}
__device__ __forceinline__ uint32_t h2u(float x, float y) {
    __half2 h = __floats2half2_rn(x, y);
    return *reinterpret_cast<uint32_t*>(&h);
}
__device__ __forceinline__ float sigf(float x) {
    return __fdividef(1.0f, 1.0f + __expf(-x));
}
__device__ __forceinline__ float tanhfast(float x) {
    return 1.0f - 2.0f * __fdividef(1.0f, __expf(2.0f * x) + 1.0f);
}

// ==========================================================================
// Convert latent -> fp16, tiled layout [(tt*16+kt)*128 + r][32]   (R10)
// ==========================================================================
__global__ void __launch_bounds__(256) conv_lat(const float* __restrict__ latent) {
    const size_t n = (size_t)T_ * B_ * 512 / 2;   // half2 units
    uint32_t* dst = reinterpret_cast<uint32_t*>(g_lat16);
    for (size_t i = (size_t)blockIdx.x * 256 + threadIdx.x; i < n;
         i += (size_t)gridDim.x * 256) {
        size_t hidx = i * 2;
        int    k    = (int)(hidx & 31);
        size_t rest = hidx >> 5;
        int    r    = (int)(rest & 127);
        size_t r2   = rest >> 7;
        int    kt   = (int)(r2 & 15);
        size_t tt   = r2 >> 4;
        size_t src  = (tt * 128 + r) * 512 + kt * 32 + k;
        float2 v = *reinterpret_cast<const float2*>(&latent[src]);
        dst[i] = h2u(v.x, v.y);
    }
}

// ==========================================================================
// Convert w_ih -> fp16 permuted smem layout (R10)
// ==========================================================================
__global__ void __launch_bounds__(256) conv_w(const float* __restrict__ w_ih) {
    const int total = 16 * 16 * 2 * 128 * 8;
    for (int d = blockIdx.x * 256 + threadIdx.x; d < total; d += gridDim.x * 256) {
        int q  = d & 7, r = (d >> 3) & 127, ks = (d >> 10) & 1;
        int kt = (d >> 11) & 15, nt = d >> 15;
        int p  = (q & 1) ? (4 + (q >> 1)) : (q >> 1);
        int k  = kt * 32 + ks * 16 + p * 2;
        int n  = nt * 128 + r;
        float2 v = *reinterpret_cast<const float2*>(&w_ih[(size_t)n * 512 + k]);
        g_w16p[d] = h2u(v.x, v.y);
    }
}

// ==========================================================================
// Phase 1: Xg = latent @ W_ih^T + bias -> fp16. 4-stage cp.async ring (R10).
// ==========================================================================
__global__ void __launch_bounds__(256, 2) xgemm_fp16(
    const float* __restrict__ b_ih, const float* __restrict__ b_hh)
{
    extern __shared__ __align__(16) unsigned char sm[];
    float* bias_s = (float*)sm;

    const int tid  = threadIdx.x;
    const int nt   = blockIdx.x & 15;
    const int tt   = blockIdx.x >> 4;
    const int n0   = nt * 128;
    const int lane = tid & 31, w = tid >> 5;
    const int mb   = (w & 3) * 32;
    const int nb2  = (w >> 2) * 64;

    if (tid < 128) bias_s[tid] = b_ih[n0 + tid] + b_hh[n0 + tid];

    const uint32_t smBase = (uint32_t)__cvta_generic_to_shared(sm);

    float c[2][8][4];
    #pragma unroll
    for (int i = 0; i < 2; i++)
        #pragma unroll
        for (int jx = 0; jx < 8; jx++)
            #pragma unroll
            for (int k = 0; k < 4; k++) c[i][jx][k] = 0.f;

    auto ISSUE = [&](int kt, int s) {
        uint32_t Aa = smBase + 512 + s * 18432;
        uint32_t Ba = Aa + 10240;
        const __half* asrc = g_lat16 + ((size_t)(tt * 16 + kt) << 12);
        #pragma unroll
        for (int i = 0; i < 2; i++) {
            int cch = tid + i * 256;
            int r = cch >> 2, c4 = cch & 3;
            cp16(Aa + r * 80 + c4 * 16, asrc + r * 32 + c4 * 8);
        }
        const uint32_t* wsrc = g_w16p + (size_t)(nt * 16 + kt) * 2048;
        #pragma unroll
        for (int i = 0; i < 2; i++) {
            int cch = tid + i * 256;
            cp16(Ba + cch * 16, wsrc + cch * 4);
        }
        asm volatile("cp.async.commit_group;");
    };

    auto COMPUTE = [&](int s) {
        const uint32_t* Au = (const uint32_t*)(sm + 512 + s * 18432);
        const uint32_t* Bs = (const uint32_t*)(sm + 512 + s * 18432 + 10240);
        #pragma unroll
        for (int ks = 0; ks < 2; ++ks) {
            uint32_t a[2][4];
            #pragma unroll
            for (int mi = 0; mi < 2; mi++) {
                int base = (mb + mi * 16 + (lane >> 2)) * 20 + ks * 8 + (lane & 3);
                a[mi][0] = Au[base];       a[mi][1] = Au[base + 160];
                a[mi][2] = Au[base + 4];   a[mi][3] = Au[base + 164];
            }
            #pragma unroll
            for (int ni = 0; ni < 8; ++ni) {
                int n = nb2 + ni * 8 + (lane >> 2);
                uint2 bv = *reinterpret_cast<const uint2*>(&Bs[(ks * 128 + n) * 8 + (lane & 3) * 2]);
                mma_f16(c[0][ni], a[0], bv.x, bv.y);
                mma_f16(c[1][ni], a[1], bv.x, bv.y);
            }
        }
    };

    ISSUE(0, 0); ISSUE(1, 1); ISSUE(2, 2);
    #pragma unroll 1
    for (int kt = 0; kt < 16; ++kt) {
        if (kt <= 13)      asm volatile("cp.async.wait_group 2;");
        else if (kt == 14) asm volatile("cp.async.wait_group 1;");
        else               asm volatile("cp.async.wait_group 0;");
        __syncthreads();
        COMPUTE(kt & 3);
        if (kt + 3 < 16) ISSUE(kt + 3, (kt + 3) & 3);
    }

    #pragma unroll
    for (int mi = 0; mi < 2; mi++) {
        #pragma unroll
        for (int ni = 0; ni < 8; ni++) {
            int r    = mb + mi * 16 + (lane >> 2);
            int colL = nb2 + ni * 8 + (lane & 3) * 2;
            float bv0 = bias_s[colL], bv1 = bias_s[colL + 1];
            size_t base = ((size_t)(tt * 128 + r)) * G4 + n0 + colL;
            *reinterpret_cast<uint32_t*>(&g_Xg[base]) =
                h2u(c[mi][ni][0] + bv0, c[mi][ni][1] + bv1);
            *reinterpret_cast<uint32_t*>(&g_Xg[base + (size_t)8 * G4]) =
                h2u(c[mi][ni][2] + bv0, c[mi][ni][3] + bv1);
        }
    }
}

// ==========================================================================
// Phase 2: persistent recurrence (R10 structure) with GATE-INTERLEAVED W
// column order: warp w's tile0 cols = [i(j) f(j)] pairs for its 4 h-cols,
// tile1 = [g(j) o(j)]. After mma, lane already holds all 4 gates of its own
// (rows rE/rE+8, col j) -> NO shuffle exchange at all.
// 128 CTAs x 256 thr. CTA (mg,cg): rows [mg*16,+16), hidden cols [cg*32,+32).
// ==========================================================================
__global__ void __launch_bounds__(256, 1) lstm_rec16(
    const float*    __restrict__ h0,
    const float*    __restrict__ c0,
    const uint32_t* __restrict__ reset,    // [B,T]
    const uint32_t* __restrict__ clearm,   // [B,T]
    const float*    __restrict__ nstd,     // [B,T]
    const float*    __restrict__ noise,    // [T,B,H]
    const float*    __restrict__ w_hh,     // [2048,512]
    float*          __restrict__ out)
{
    extern __shared__ __align__(16) unsigned char sm[];
    __half* W_s = (__half*)sm;                       // 196608 B (init only)
    __half* A_s = (__half*)(sm + 196608);            // 16 x 520 halves

    const int tid  = threadIdx.x;
    const int cb   = blockIdx.x;
    const int mg   = cb >> 4, cg = cb & 15;
    const int b0   = mg * 16, j0 = cg * 32;
    const int lane = tid & 31, w = tid >> 5;
    const unsigned FM = 0xFFFFFFFFu;

    // ---- W_s fill (once), GATE-INTERLEAVED col order:
    //   atom col c = wp*16 + ti*8 + p  ->  gate (ti*2 + (p&1)), h-col wp*4 + (p>>1)
    for (int e = tid; e < 4096; e += 256) {
        int ks = e >> 7, c = e & 127;
        int wp = c >> 4, idx = c & 15;
        int ti = idx >> 3, p = idx & 7;
        int n  = (ti * 2 + (p & 1)) * 512 + j0 + wp * 4 + (p >> 1);
        const float4* wpn = reinterpret_cast<const float4*>(&w_hh[(size_t)n * 512 + ks * 16]);
        float4 w0 = wpn[0], w1 = wpn[1], w2 = wpn[2], w3 = wpn[3];
        uint4 lo, hi;
        lo.x = h2u(w0.x, w0.y); lo.y = h2u(w0.z, w0.w);
        lo.z = h2u(w1.x, w1.y); lo.w = h2u(w1.z, w1.w);
        hi.x = h2u(w2.x, w2.y); hi.y = h2u(w2.z, w2.w);
        hi.z = h2u(w3.x, w3.y); hi.w = h2u(w3.z, w3.w);
        char* base = (char*)W_s + (size_t)(ks * 128 + c) * 48;
        *reinterpret_cast<uint4*>(base)      = lo;
        *reinterpret_cast<uint4*>(base + 16) = hi;
    }
    __syncthreads();

    // ---- load all W fragments into registers
    const uint32_t smBase = (uint32_t)__cvta_generic_to_shared(sm);
    const uint32_t As_sa  = smBase + 196608;
    const int mq = lane >> 3, rl = lane & 7;
    const int rowL = (mq & 1) * 8 + rl;
    const int koff = (mq >> 1) * 8;
    const uint32_t aAddr0 = As_sa + rowL * 1040 + koff * 2;
    const uint32_t bAddr0 = smBase + (w * 16 + rowL) * 48 + koff * 2;
    uint32_t bb[32][4];
    #pragma unroll
    for (int ks = 0; ks < 32; ++ks)
        ldsm4(bb[ks], bAddr0 + ks * 6144);

    // ---- epilogue lane mapping (gates now land in-lane; no shuffles)
    const int rE = lane >> 2, jE = lane & 3;
    const int bA = b0 + rE, bB = bA + 8;
    const int j  = j0 + w * 4 + jE;

    // ---- init h/c with step-0 preprocessing
    float cst0, cst1;
    {
        float hA = h0[bA * H_ + j], cA = c0[bA * H_ + j];
        float hB = h0[bB * H_ + j], cB = c0[bB * H_ + j];
        bool mA = ((reset[bA * T_] | clearm[bA * T_]) != 0u);
        bool mB = ((reset[bB * T_] | clearm[bB * T_]) != 0u);
        if (mA) { hA = cA = 0.f; }
        if (mB) { hB = cB = 0.f; }
        float nzA = noise[(size_t)bA * H_ + j] * nstd[bA * T_];
        float nzB = noise[(size_t)bB * H_ + j] * nstd[bB * T_];
        hA += nzA; cA += nzA;
        hB += nzB; cB += nzB;
        g_h2[0][bA * H_ + j] = __float2half_rn(hA);
        g_h2[0][bB * H_ + j] = __float2half_rn(hB);
        cst0 = cA; cst1 = cB;
    }
    __syncthreads();
    if (tid == 0)
        asm volatile("st.release.gpu.global.u32 [%0], %1;"
                     :: "l"(&g_flag[mg][0][cg]), "r"(1u) : "memory");

    const int stR = tid >> 6;
    const int stC = tid & 63;

    for (int t = 0; t < T_; ++t) {
        // ---- prefetch (independent of h[t]) ----
        size_t xbA = ((size_t)t * B_ + bA) * G4 + j;
        size_t xbB = ((size_t)t * B_ + bB) * G4 + j;
        float xI0 = __half2float(g_Xg[xbA]),        xI1 = __half2float(g_Xg[xbB]);
        float xF0 = __half2float(g_Xg[xbA + 512]),  xF1 = __half2float(g_Xg[xbB + 512]);
        float xG0 = __half2float(g_Xg[xbA + 1024]), xG1 = __half2float(g_Xg[xbB + 1024]);
        float xO0 = __half2float(g_Xg[xbA + 1536]), xO1 = __half2float(g_Xg[xbB + 1536]);
        unsigned mN0 = 0, mN1 = 0;
        float sN0 = 0.f, sN1 = 0.f, nz0 = 0.f, nz1 = 0.f;
        if (t + 1 < T_) {
            mN0 = reset[bA * T_ + t + 1] | clearm[bA * T_ + t + 1];
            mN1 = reset[bB * T_ + t + 1] | clearm[bB * T_ + t + 1];
            sN0 = nstd[bA * T_ + t + 1];
            sN1 = nstd[bB * T_ + t + 1];
            nz0 = noise[((size_t)(t + 1) * B_ + bA) * H_ + j];
            nz1 = noise[((size_t)(t + 1) * B_ + bB) * H_ + j];
        }

        // ---- parallel flag poll (all warps; lane<16 each watch one rank) ----
        {
            const unsigned* fp = &g_flag[mg][t][lane & 15];
            unsigned v = 1;
            const bool mine = lane < NG;
            #pragma unroll 1
            do {
                if (mine)
                    asm volatile("ld.acquire.gpu.global.u32 %0, [%1];"
                                 : "=r"(v) : "l"(fp) : "memory");
            } while (!__all_sync(FM, v != 0));
        }
        // rolling reset of stale flags (safe: all peers passed wait[t-1])
        if (cg == 0 && w == 0 && t >= 1 && lane < NG)
            g_flag[mg][t - 1][lane] = 0;

        // ---- stage h tile [16][512] fp16 via cp.async (per-warp, post-acquire)
        const __half* __restrict__ hsrc = g_h2[t & 1];
        #pragma unroll
        for (int i = 0; i < 4; i++) {
            int r = stR + i * 4;
            cp16(As_sa + r * 1040 + stC * 16, &hsrc[(b0 + r) * H_ + stC * 8]);
        }
        asm volatile("cp.async.commit_group;");
        asm volatile("cp.async.wait_group 0;");
        __syncthreads();

        // ---- GEMM: 32 ksteps, 4 accumulation chains ----
        float a0A[4] = {0.f, 0.f, 0.f, 0.f}, a1A[4] = {0.f, 0.f, 0.f, 0.f};
        float a0B[4] = {0.f, 0.f, 0.f, 0.f}, a1B[4] = {0.f, 0.f, 0.f, 0.f};
        #pragma unroll
        for (int ks = 0; ks < 32; ks += 2) {
            uint32_t a[4], a2[4];
            ldsm4(a,  aAddr0 + ks * 32);
            ldsm4(a2, aAddr0 + ks * 32 + 32);
            mma_f16(a0A, a,  bb[ks][0],     bb[ks][2]);
            mma_f16(a1A, a,  bb[ks][1],     bb[ks][3]);
            mma_f16(a0B, a2, bb[ks + 1][0], bb[ks + 1][2]);
            mma_f16(a1B, a2, bb[ks + 1][1], bb[ks + 1][3]);
        }
        // acc0 = {i(r,j), f(r,j), i(r+8,j), f(r+8,j)}; acc1 = {g, o, g, o}
        float gi0 = a0A[0] + a0B[0], gf0 = a0A[1] + a0B[1];
        float gi1 = a0A[2] + a0B[2], gf1 = a0A[3] + a0B[3];
        float gg0 = a1A[0] + a1B[0], go0 = a1A[1] + a1B[1];
        float gg1 = a1A[2] + a1B[2], go1 = a1A[3] + a1B[3];

        // ---- gates + state update + next-step preprocessing ----
        float iA = sigf(gi0 + xI0),     iB = sigf(gi1 + xI1);
        float fA = sigf(gf0 + xF0),     fB = sigf(gf1 + xF1);
        float gA = tanhfast(gg0 + xG0), gB = tanhfast(gg1 + xG1);
        float oA = sigf(go0 + xO0),     oB = sigf(go1 + xO1);

        float cnA = fA * cst0 + iA * gA;
        float cnB = fB * cst1 + iB * gB;
        float hnA = oA * tanhfast(cnA);
        float hnB = oB * tanhfast(cnB);

        if (t + 1 < T_) {
            float hwA = mN0 ? 0.f : hnA, cwA = mN0 ? 0.f : cnA;
            float hwB = mN1 ? 0.f : hnB, cwB = mN1 ? 0.f : cnB;
            hwA += nz0 * sN0; cwA += nz0 * sN0;
            hwB += nz1 * sN1; cwB += nz1 * sN1;
            g_h2[(t + 1) & 1][bA * H_ + j] = __float2half_rn(hwA);
            g_h2[(t + 1) & 1][bB * H_ + j] = __float2half_rn(hwB);
            cst0 = cwA; cst1 = cwB;
        }

        __syncthreads();
        if (tid == 0)
            asm volatile("st.release.gpu.global.u32 [%0], %1;"
                         :: "l"(&g_flag[mg][t + 1][cg]), "r"(1u) : "memory");

        // ---- off-critical-path output stores ----
        out[((size_t)t * B_ + bA) * H_ + j] = hnA;
        out[((size_t)t * B_ + bB) * H_ + j] = hnB;
        if (t == T_ - 1) {
            out[(size_t)T_ * (B_ * H_)           + bA * H_ + j] = hnA;
            out[(size_t)T_ * (B_ * H_)           + bB * H_ + j] = hnB;
            out[(size_t)T_ * (B_ * H_) + B_ * H_ + bA * H_ + j] = cnA;
            out[(size_t)T_ * (B_ * H_) + B_ * H_ + bB * H_ + j] = cnB;
        }
    }

    // ---- end sync + restore flags to zero for graph replays ----
    if (cg == 0 && w == 0) {
        const unsigned* fp = &g_flag[mg][T_][lane & 15];
        unsigned v = 1;
        const bool mine = lane < NG;
        #pragma unroll 1
        do {
            if (mine)
                asm volatile("ld.acquire.gpu.global.u32 %0, [%1];"
                             : "=r"(v) : "l"(fp) : "memory");
        } while (!__all_sync(FM, v != 0));
        if (lane < NG) {
            g_flag[mg][T_ - 1][lane] = 0;
            g_flag[mg][T_][lane]     = 0;
        }
    }
}

// ==========================================================================
extern "C" void kernel_launch(void* const* d_in, const int* in_sizes, int n_in,
                              void* d_out, int out_size) {
    (void)in_sizes; (void)n_in; (void)out_size;
    const float*    latent = (const float*)d_in[0];
    const float*    h0     = (const float*)d_in[1];
    const float*    c0     = (const float*)d_in[2];
    const uint32_t* reset  = (const uint32_t*)d_in[3];
    const uint32_t* clearm = (const uint32_t*)d_in[4];
    const float*    nstd   = (const float*)d_in[5];
    const float*    noise  = (const float*)d_in[6];
    const float*    w_ih   = (const float*)d_in[7];
    const float*    w_hh   = (const float*)d_in[8];
    const float*    b_ih   = (const float*)d_in[9];
    const float*    b_hh   = (const float*)d_in[10];
    float* out = (float*)d_out;

    const int smem1 = 512 + 4 * 18432;                 // 74240 B
    const int smem2 = 196608 + 16640;                  // 213248 B
    cudaFuncSetAttribute(xgemm_fp16, cudaFuncAttributeMaxDynamicSharedMemorySize, smem1);
    cudaFuncSetAttribute(lstm_rec16, cudaFuncAttributeMaxDynamicSharedMemorySize, smem2);

    conv_lat<<<4096, 256>>>(latent);
    conv_w<<<512, 256>>>(w_ih);
    xgemm_fp16<<<512 * 16, 256, smem1>>>(b_ih, b_hh);
    lstm_rec16<<<128, 256, smem2>>>(h0, c0, reset, clearm, nstd, noise, w_hh, out);
}